// round 6
// baseline (speedup 1.0000x reference)
#include <cuda_runtime.h>
#include <cstdint>
#include <cstddef>

// ---------------------------------------------------------------------------
// Problem constants
// ---------------------------------------------------------------------------
namespace {
constexpr int N_   = 50000;
constexpr int D_   = 160;     // = H*C
constexpr int H_   = 5;
constexpr int E_   = 800000;
constexpr int ED_  = 16;
constexpr int HID_ = 512;
constexpr float EPS_   = 1e-5f;
constexpr float SLOPE_ = 0.2f;
}

// ---------------------------------------------------------------------------
// Scratch buffers (device globals -- no allocation allowed)
// ---------------------------------------------------------------------------
__device__ float    g_xlr  [(size_t)N_ * 320];   // [N][320]: cols 0..159 = xl, 160..319 = xr
__device__ float    g_score[(size_t)E_ * H_];    // scores, then ex (in place)
__device__ unsigned g_mx   [N_ * H_];            // ordered-uint encoded segment max
__device__ float    g_denom[N_ * H_];
__device__ float    g_agg  [(size_t)N_ * D_];    // attention agg, later reused for MLP2 out
__device__ float    g_out1 [(size_t)N_ * D_];    // after first LN (residual for final LN)
__device__ float    g_hid  [(size_t)N_ * HID_];
__device__ float    g_Wcat [D_ * 320];           // [Wl | Wr]
__device__ float    g_bcat [320];

// ---------------------------------------------------------------------------
// Helpers
// ---------------------------------------------------------------------------
// Order-preserving float <-> uint encoding for atomicMax on floats
__device__ __forceinline__ unsigned fenc(float f) {
    unsigned u = __float_as_uint(f);
    return (u & 0x80000000u) ? ~u : (u | 0x80000000u);
}
__device__ __forceinline__ float fdec(unsigned u) {
    return (u & 0x80000000u) ? __uint_as_float(u & 0x7FFFFFFFu)
                             : __uint_as_float(~u);
}

__device__ __forceinline__ float selu_f(float x) {
    const float a = 1.6732632423543772f;
    const float s = 1.0507009873554805f;
    return x > 0.f ? s * x : s * a * (__expf(x) - 1.f);
}

// ---------------------------------------------------------------------------
// Init: zero agg + denom, fill mx with encoded -inf
// ---------------------------------------------------------------------------
__global__ void init_k() {
    int i = blockIdx.x * blockDim.x + threadIdx.x;
    if (i < N_ * D_ / 4)
        reinterpret_cast<float4*>(g_agg)[i] = make_float4(0.f, 0.f, 0.f, 0.f);
    if (i < N_ * H_) {
        g_denom[i] = 0.f;
        g_mx[i]    = 0x007FFFFFu;   // fenc(-inf)
    }
}

// Concatenate Wl|Wr and bl|br so node projection is one 320-wide GEMM
__global__ void prep_w(const float* __restrict__ Wl, const float* __restrict__ bl,
                       const float* __restrict__ Wr, const float* __restrict__ br) {
    int i = blockIdx.x * blockDim.x + threadIdx.x;
    if (i < D_ * 320) {
        int k = i / 320, c = i - k * 320;
        g_Wcat[i] = (c < D_) ? Wl[k * D_ + c] : Wr[k * D_ + (c - D_)];
    }
    if (i < 320)
        g_bcat[i] = (i < D_) ? bl[i] : br[i - D_];
}

// ---------------------------------------------------------------------------
// SGEMM: C[M,Nc] = A[M,K] @ B[K,Nc] + bias (+optional SELU)
// BM=128, BN=64, BK=32, 256 threads, 8x4 microtile.
// A transposed into smem with pad-4 stride (keeps 16B-aligned vector LDS,
// bounded 4-way STS conflict on the transpose only).
// ---------------------------------------------------------------------------
template<bool DOSELU>
__global__ __launch_bounds__(256)
void sgemm_k(const float* __restrict__ A, const float* __restrict__ B,
             const float* __restrict__ bias, float* __restrict__ C,
             int M, int Nc, int K)
{
    constexpr int BM = 128, BN = 64, BK = 32, LDA = BM + 4;
    __shared__ float As[BK * LDA];
    __shared__ float Bs[BK * BN];

    const int tid = threadIdx.x;
    const int bm0 = blockIdx.y * BM;
    const int bn0 = blockIdx.x * BN;

    const int ra = tid >> 3;          // 0..31  (A load row within 32-row slab)
    const int ka = (tid & 7) << 2;    // 0,4,...,28
    const int kb = tid >> 4;          // 0..15  (B load k)
    const int nb = (tid & 15) << 2;   // 0..60
    const int ty = tid >> 4;          // 0..15  (microtile row group)
    const int tx = tid & 15;          // 0..15  (microtile col group)

    float acc[8][4];
#pragma unroll
    for (int i = 0; i < 8; i++)
#pragma unroll
        for (int j = 0; j < 4; j++) acc[i][j] = 0.f;

    for (int k0 = 0; k0 < K; k0 += BK) {
        // --- load A tile (coalesced 128B per 8 lanes), transpose into smem
#pragma unroll
        for (int r = 0; r < 4; r++) {
            int row = bm0 + ra + r * 32;
            float4 v = make_float4(0.f, 0.f, 0.f, 0.f);
            if (row < M)
                v = *reinterpret_cast<const float4*>(A + (size_t)row * K + k0 + ka);
            int sm = ra + r * 32;
            As[(ka + 0) * LDA + sm] = v.x;
            As[(ka + 1) * LDA + sm] = v.y;
            As[(ka + 2) * LDA + sm] = v.z;
            As[(ka + 3) * LDA + sm] = v.w;
        }
        // --- load B tile (row-major, guarded on columns)
        {
            int colb = bn0 + nb;
#pragma unroll
            for (int r = 0; r < 2; r++) {
                int k = kb + r * 16;
                float4 v = make_float4(0.f, 0.f, 0.f, 0.f);
                if (colb < Nc)
                    v = *reinterpret_cast<const float4*>(B + (size_t)(k0 + k) * Nc + colb);
                *reinterpret_cast<float4*>(&Bs[k * BN + nb]) = v;
            }
        }
        __syncthreads();

#pragma unroll 8
        for (int kk = 0; kk < BK; kk++) {
            float4 a0 = *reinterpret_cast<const float4*>(&As[kk * LDA + ty * 4]);
            float4 a1 = *reinterpret_cast<const float4*>(&As[kk * LDA + 64 + ty * 4]);
            float4 b4 = *reinterpret_cast<const float4*>(&Bs[kk * BN + tx * 4]);
            float ar[8]  = {a0.x, a0.y, a0.z, a0.w, a1.x, a1.y, a1.z, a1.w};
            float brg[4] = {b4.x, b4.y, b4.z, b4.w};
#pragma unroll
            for (int i = 0; i < 8; i++)
#pragma unroll
                for (int j = 0; j < 4; j++)
                    acc[i][j] = fmaf(ar[i], brg[j], acc[i][j]);
        }
        __syncthreads();
    }

    // --- epilogue: +bias (+SELU), vectorized store
    int ncol = bn0 + tx * 4;
    if (ncol >= Nc) return;
    float4 bv = *reinterpret_cast<const float4*>(bias + ncol);
#pragma unroll
    for (int i = 0; i < 8; i++) {
        int row = bm0 + ((i < 4) ? (ty * 4 + i) : (64 + ty * 4 + (i - 4)));
        if (row < M) {
            float4 o = make_float4(acc[i][0] + bv.x, acc[i][1] + bv.y,
                                   acc[i][2] + bv.z, acc[i][3] + bv.w);
            if (DOSELU) {
                o.x = selu_f(o.x); o.y = selu_f(o.y);
                o.z = selu_f(o.z); o.w = selu_f(o.w);
            }
            *reinterpret_cast<float4*>(C + (size_t)row * Nc + ncol) = o;
        }
    }
}

// ---------------------------------------------------------------------------
// Edge pass 1: score[e,h] = att . leaky_relu(xl[src]+xr[dst]+ea), atomicMax mx
// One warp per edge; We (16x160, 10KB) staged in smem; ea computed on the fly.
// ---------------------------------------------------------------------------
__global__ __launch_bounds__(256)
void edge_score_k(const int* __restrict__ ei, const float* __restrict__ eattr,
                  const float* __restrict__ We, const float* __restrict__ att)
{
    __shared__ float We_s[ED_ * D_];
    __shared__ float att_s[D_];
    for (int i = threadIdx.x; i < ED_ * D_; i += 256) We_s[i] = We[i];
    if (threadIdx.x < D_) att_s[threadIdx.x] = att[threadIdx.x];
    __syncthreads();

    const int lane = threadIdx.x & 31;
    int w        = (blockIdx.x * 256 + threadIdx.x) >> 5;
    const int nw = (gridDim.x * 256) >> 5;

    for (int e = w; e < E_; e += nw) {
        int src = ei[e], dst = ei[E_ + e];
        const float* xl = g_xlr + (size_t)src * 320;
        const float* xr = g_xlr + (size_t)dst * 320 + 160;

        float ew[ED_];
        const float4* ep = reinterpret_cast<const float4*>(eattr + (size_t)e * ED_);
#pragma unroll
        for (int q = 0; q < ED_ / 4; q++) {
            float4 v = __ldg(ep + q);
            ew[4*q] = v.x; ew[4*q+1] = v.y; ew[4*q+2] = v.z; ew[4*q+3] = v.w;
        }

        float acc[H_];
#pragma unroll
        for (int h = 0; h < H_; h++) {
            int col = h * 32 + lane;
            float v = xl[col] + xr[col];
#pragma unroll
            for (int k = 0; k < ED_; k++)
                v = fmaf(ew[k], We_s[k * D_ + col], v);
            float lr = v > 0.f ? v : SLOPE_ * v;
            acc[h] = att_s[col] * lr;
        }
#pragma unroll
        for (int h = 0; h < H_; h++)
#pragma unroll
            for (int o = 16; o > 0; o >>= 1)
                acc[h] += __shfl_xor_sync(0xffffffffu, acc[h], o);

        if (lane == 0) {
            unsigned* mxp = g_mx + (size_t)dst * H_;
            float*    sp  = g_score + (size_t)e * H_;
#pragma unroll
            for (int h = 0; h < H_; h++) {
                sp[h] = acc[h];
                atomicMax(&mxp[h], fenc(acc[h]));
            }
        }
    }
}

// ---------------------------------------------------------------------------
// Edge pass 2: ex = exp(score - mx[dst]); denom[dst] += ex  (in-place ex)
// ---------------------------------------------------------------------------
__global__ void edge_exp_k(const int* __restrict__ ei)
{
    int i = blockIdx.x * blockDim.x + threadIdx.x;
    if (i >= E_ * H_) return;
    int e = i / H_;
    int h = i - e * H_;
    int dst = ei[E_ + e];
    float ex = __expf(g_score[i] - fdec(g_mx[dst * H_ + h]));
    g_score[i] = ex;
    atomicAdd(&g_denom[dst * H_ + h], ex);
}

// ---------------------------------------------------------------------------
// Edge pass 3: agg[dst] += alpha[e,h] * xl[src]  (vector f32x4 REDs)
// One warp per edge; lane l handles cols [4l,4l+3] (head l/8) and,
// for l<8, cols [128+4l, 128+4l+3] (head 4).
// ---------------------------------------------------------------------------
__global__ __launch_bounds__(256)
void edge_agg_k(const int* __restrict__ ei)
{
    const int lane = threadIdx.x & 31;
    int w        = (blockIdx.x * 256 + threadIdx.x) >> 5;
    const int nw = (gridDim.x * 256) >> 5;

    for (int e = w; e < E_; e += nw) {
        int src = ei[e], dst = ei[E_ + e];
        float al = 0.f;
        if (lane < H_)
            al = g_score[(size_t)e * H_ + lane] / g_denom[(size_t)dst * H_ + lane];
        float a0 = __shfl_sync(0xffffffffu, al, lane >> 3);  // head of my group
        float a4 = __shfl_sync(0xffffffffu, al, 4);          // head 4

        const float4* xl4 = reinterpret_cast<const float4*>(g_xlr + (size_t)src * 320);
        float4*       ag4 = reinterpret_cast<float4*>(g_agg + (size_t)dst * 160);
        {
            float4 v = __ldg(xl4 + lane);
            asm volatile("red.global.add.v4.f32 [%0], {%1,%2,%3,%4};" ::
                         "l"(ag4 + lane),
                         "f"(a0 * v.x), "f"(a0 * v.y), "f"(a0 * v.z), "f"(a0 * v.w)
                         : "memory");
        }
        if (lane < 8) {
            float4 v = __ldg(xl4 + 32 + lane);
            asm volatile("red.global.add.v4.f32 [%0], {%1,%2,%3,%4};" ::
                         "l"(ag4 + 32 + lane),
                         "f"(a4 * v.x), "f"(a4 * v.y), "f"(a4 * v.z), "f"(a4 * v.w)
                         : "memory");
        }
    }
}

// ---------------------------------------------------------------------------
// LayerNorms (warp per row)
// ---------------------------------------------------------------------------
__global__ void ln1_k(const float* __restrict__ x, const float* __restrict__ bgat,
                      const float* __restrict__ g, const float* __restrict__ b)
{
    const int lane = threadIdx.x & 31;
    int row = (blockIdx.x * blockDim.x + threadIdx.x) >> 5;
    if (row >= N_) return;
    const float* xr = x     + (size_t)row * D_;
    const float* ar = g_agg + (size_t)row * D_;
    float v[H_];
    float s = 0.f, s2 = 0.f;
#pragma unroll
    for (int h = 0; h < H_; h++) {
        int c = h * 32 + lane;
        float t = xr[c] + ar[c] + __ldg(&bgat[c]);
        v[h] = t; s += t; s2 = fmaf(t, t, s2);
    }
#pragma unroll
    for (int o = 16; o > 0; o >>= 1) {
        s  += __shfl_xor_sync(0xffffffffu, s,  o);
        s2 += __shfl_xor_sync(0xffffffffu, s2, o);
    }
    float mean = s * (1.f / D_);
    float var  = s2 * (1.f / D_) - mean * mean;
    float inv  = rsqrtf(var + EPS_);
    float* op = g_out1 + (size_t)row * D_;
#pragma unroll
    for (int h = 0; h < H_; h++) {
        int c = h * 32 + lane;
        op[c] = (v[h] - mean) * inv * __ldg(&g[c]) + __ldg(&b[c]);
    }
}

__global__ void ln_hid_k(const float* __restrict__ g, const float* __restrict__ b)
{
    const int lane = threadIdx.x & 31;
    int row = (blockIdx.x * blockDim.x + threadIdx.x) >> 5;
    if (row >= N_) return;
    float* hp = g_hid + (size_t)row * HID_;
    float4 v[4];
    float s = 0.f, s2 = 0.f;
#pragma unroll
    for (int j = 0; j < 4; j++) {
        v[j] = *reinterpret_cast<const float4*>(hp + j * 128 + lane * 4);
        s += v[j].x + v[j].y + v[j].z + v[j].w;
        s2 = fmaf(v[j].x, v[j].x, fmaf(v[j].y, v[j].y,
             fmaf(v[j].z, v[j].z, fmaf(v[j].w, v[j].w, s2))));
    }
#pragma unroll
    for (int o = 16; o > 0; o >>= 1) {
        s  += __shfl_xor_sync(0xffffffffu, s,  o);
        s2 += __shfl_xor_sync(0xffffffffu, s2, o);
    }
    float mean = s * (1.f / HID_);
    float var  = s2 * (1.f / HID_) - mean * mean;
    float inv  = rsqrtf(var + EPS_);
#pragma unroll
    for (int j = 0; j < 4; j++) {
        int c = j * 128 + lane * 4;
        float4 gg = __ldg(reinterpret_cast<const float4*>(g + c));
        float4 bb = __ldg(reinterpret_cast<const float4*>(b + c));
        float4 o;
        o.x = (v[j].x - mean) * inv * gg.x + bb.x;
        o.y = (v[j].y - mean) * inv * gg.y + bb.y;
        o.z = (v[j].z - mean) * inv * gg.z + bb.z;
        o.w = (v[j].w - mean) * inv * gg.w + bb.w;
        *reinterpret_cast<float4*>(hp + c) = o;
    }
}

// final: out = LN(out1 + mlp) ; mlp lives in g_agg (reused)
__global__ void ln2_k(const float* __restrict__ g, const float* __restrict__ b,
                      float* __restrict__ out)
{
    const int lane = threadIdx.x & 31;
    int row = (blockIdx.x * blockDim.x + threadIdx.x) >> 5;
    if (row >= N_) return;
    const float* r1 = g_out1 + (size_t)row * D_;
    const float* r2 = g_agg  + (size_t)row * D_;
    float v[H_];
    float s = 0.f, s2 = 0.f;
#pragma unroll
    for (int h = 0; h < H_; h++) {
        int c = h * 32 + lane;
        float t = r1[c] + r2[c];
        v[h] = t; s += t; s2 = fmaf(t, t, s2);
    }
#pragma unroll
    for (int o = 16; o > 0; o >>= 1) {
        s  += __shfl_xor_sync(0xffffffffu, s,  o);
        s2 += __shfl_xor_sync(0xffffffffu, s2, o);
    }
    float mean = s * (1.f / D_);
    float var  = s2 * (1.f / D_) - mean * mean;
    float inv  = rsqrtf(var + EPS_);
    float* op = out + (size_t)row * D_;
#pragma unroll
    for (int h = 0; h < H_; h++) {
        int c = h * 32 + lane;
        op[c] = (v[h] - mean) * inv * __ldg(&g[c]) + __ldg(&b[c]);
    }
}

// ---------------------------------------------------------------------------
// Launch
// ---------------------------------------------------------------------------
extern "C" void kernel_launch(void* const* d_in, const int* in_sizes, int n_in,
                              void* d_out, int out_size)
{
    const float* x     = (const float*)d_in[0];
    const int*   ei    = (const int*)  d_in[1];
    const float* eattr = (const float*)d_in[2];
    // d_in[3] = u, d_in[4] = batch : unused by the reference
    const float* Wl    = (const float*)d_in[5];
    const float* bl    = (const float*)d_in[6];
    const float* Wr    = (const float*)d_in[7];
    const float* br    = (const float*)d_in[8];
    const float* We    = (const float*)d_in[9];
    const float* att   = (const float*)d_in[10];
    const float* bgat  = (const float*)d_in[11];
    const float* g1    = (const float*)d_in[12];
    const float* b1    = (const float*)d_in[13];
    const float* Wm1   = (const float*)d_in[14];
    const float* bm1   = (const float*)d_in[15];
    const float* gm    = (const float*)d_in[16];
    const float* bm    = (const float*)d_in[17];
    const float* Wm2   = (const float*)d_in[18];
    const float* bm2   = (const float*)d_in[19];
    const float* g2    = (const float*)d_in[20];
    const float* b2    = (const float*)d_in[21];
    float* out = (float*)d_out;

    float *xlr, *Wcat, *bcat, *out1, *hid, *agg;
    cudaGetSymbolAddress((void**)&xlr,  g_xlr);
    cudaGetSymbolAddress((void**)&Wcat, g_Wcat);
    cudaGetSymbolAddress((void**)&bcat, g_bcat);
    cudaGetSymbolAddress((void**)&out1, g_out1);
    cudaGetSymbolAddress((void**)&hid,  g_hid);
    cudaGetSymbolAddress((void**)&agg,  g_agg);

    // init scratch (agg=0, denom=0, mx=-inf) + weight concat
    init_k<<<(N_ * D_ / 4 + 255) / 256, 256>>>();
    prep_w<<<(D_ * 320 + 255) / 256, 256>>>(Wl, bl, Wr, br);

    // xl|xr = x @ [Wl|Wr] + [bl|br]   -> g_xlr [N,320]
    sgemm_k<false><<<dim3(320 / 64, (N_ + 127) / 128), 256>>>(
        x, Wcat, bcat, xlr, N_, 320, D_);

    // GATv2 attention
    edge_score_k<<<1184, 256>>>(ei, eattr, We, att);
    edge_exp_k<<<(E_ * H_ + 255) / 256, 256>>>(ei);
    edge_agg_k<<<1184, 256>>>(ei);

    // out1 = LN(x + agg + b_gat)
    ln1_k<<<(N_ + 7) / 8, 256>>>(x, bgat, g1, b1);

    // hid = selu(out1 @ W_m1 + b_m1), then LN in place
    sgemm_k<true><<<dim3(HID_ / 64, (N_ + 127) / 128), 256>>>(
        out1, Wm1, bm1, hid, N_, HID_, D_);
    ln_hid_k<<<(N_ + 7) / 8, 256>>>(gm, bm);

    // mlp = hid @ W_m2 + b_m2  (reuse g_agg)
    sgemm_k<false><<<dim3((D_ + 63) / 64, (N_ + 127) / 128), 256>>>(
        hid, Wm2, bm2, agg, N_, D_, HID_);

    // out = LN(out1 + mlp)
    ln2_k<<<(N_ + 7) / 8, 256>>>(g2, b2, out);
}

// round 7
// speedup vs baseline: 1.0511x; 1.0511x over previous
#include <cuda_runtime.h>
#include <cstdint>
#include <cstddef>

// ---------------------------------------------------------------------------
// Problem constants
// ---------------------------------------------------------------------------
namespace {
constexpr int N_   = 50000;
constexpr int D_   = 160;     // = H*C
constexpr int H_   = 5;
constexpr int E_   = 800000;
constexpr int ED_  = 16;
constexpr int HID_ = 512;
constexpr float EPS_   = 1e-5f;
constexpr float SLOPE_ = 0.2f;
}

// ---------------------------------------------------------------------------
// Scratch buffers (device globals -- no allocation allowed)
// ---------------------------------------------------------------------------
__device__ float    g_xlr  [(size_t)N_ * 320];   // [N][320]: cols 0..159 = xl, 160..319 = xr
__device__ float    g_score[(size_t)E_ * H_];    // scores, then ex (in place)
__device__ unsigned g_mx   [N_ * H_];            // ordered-uint encoded segment max
__device__ float    g_denom[N_ * H_];
__device__ float    g_agg  [(size_t)N_ * D_];    // attention agg, later reused for MLP2 out
__device__ float    g_out1 [(size_t)N_ * D_];    // after first LN (residual for final LN)
__device__ float    g_hid  [(size_t)N_ * HID_];
__device__ float    g_Wcat [D_ * 320];           // [Wl | Wr]
__device__ float    g_bcat [320];

// ---------------------------------------------------------------------------
// Helpers
// ---------------------------------------------------------------------------
__device__ __forceinline__ unsigned fenc(float f) {
    unsigned u = __float_as_uint(f);
    return (u & 0x80000000u) ? ~u : (u | 0x80000000u);
}
__device__ __forceinline__ float fdec(unsigned u) {
    return (u & 0x80000000u) ? __uint_as_float(u & 0x7FFFFFFFu)
                             : __uint_as_float(~u);
}

__device__ __forceinline__ float selu_f(float x) {
    const float a = 1.6732632423543772f;
    const float s = 1.0507009873554805f;
    return x > 0.f ? s * x : s * a * (__expf(x) - 1.f);
}

// ---------------------------------------------------------------------------
// Init: zero agg + denom, fill mx with encoded -inf
// ---------------------------------------------------------------------------
__global__ void init_k() {
    int i = blockIdx.x * blockDim.x + threadIdx.x;
    if (i < N_ * D_ / 4)
        reinterpret_cast<float4*>(g_agg)[i] = make_float4(0.f, 0.f, 0.f, 0.f);
    if (i < N_ * H_) {
        g_denom[i] = 0.f;
        g_mx[i]    = 0x007FFFFFu;   // fenc(-inf)
    }
}

__global__ void prep_w(const float* __restrict__ Wl, const float* __restrict__ bl,
                       const float* __restrict__ Wr, const float* __restrict__ br) {
    int i = blockIdx.x * blockDim.x + threadIdx.x;
    if (i < D_ * 320) {
        int k = i / 320, c = i - k * 320;
        g_Wcat[i] = (c < D_) ? Wl[k * D_ + c] : Wr[k * D_ + (c - D_)];
    }
    if (i < 320)
        g_bcat[i] = (i < D_) ? bl[i] : br[i - D_];
}

// ---------------------------------------------------------------------------
// SGEMM: C[M,Nc] = A[M,K] @ B[K,Nc] + bias (+optional SELU)
// ---------------------------------------------------------------------------
template<bool DOSELU>
__global__ __launch_bounds__(256)
void sgemm_k(const float* __restrict__ A, const float* __restrict__ B,
             const float* __restrict__ bias, float* __restrict__ C,
             int M, int Nc, int K)
{
    constexpr int BM = 128, BN = 64, BK = 32, LDA = BM + 4;
    __shared__ float As[BK * LDA];
    __shared__ float Bs[BK * BN];

    const int tid = threadIdx.x;
    const int bm0 = blockIdx.y * BM;
    const int bn0 = blockIdx.x * BN;

    const int ra = tid >> 3;
    const int ka = (tid & 7) << 2;
    const int kb = tid >> 4;
    const int nb = (tid & 15) << 2;
    const int ty = tid >> 4;
    const int tx = tid & 15;

    float acc[8][4];
#pragma unroll
    for (int i = 0; i < 8; i++)
#pragma unroll
        for (int j = 0; j < 4; j++) acc[i][j] = 0.f;

    for (int k0 = 0; k0 < K; k0 += BK) {
#pragma unroll
        for (int r = 0; r < 4; r++) {
            int row = bm0 + ra + r * 32;
            float4 v = make_float4(0.f, 0.f, 0.f, 0.f);
            if (row < M)
                v = *reinterpret_cast<const float4*>(A + (size_t)row * K + k0 + ka);
            int sm = ra + r * 32;
            As[(ka + 0) * LDA + sm] = v.x;
            As[(ka + 1) * LDA + sm] = v.y;
            As[(ka + 2) * LDA + sm] = v.z;
            As[(ka + 3) * LDA + sm] = v.w;
        }
        {
            int colb = bn0 + nb;
#pragma unroll
            for (int r = 0; r < 2; r++) {
                int k = kb + r * 16;
                float4 v = make_float4(0.f, 0.f, 0.f, 0.f);
                if (colb < Nc)
                    v = *reinterpret_cast<const float4*>(B + (size_t)(k0 + k) * Nc + colb);
                *reinterpret_cast<float4*>(&Bs[k * BN + nb]) = v;
            }
        }
        __syncthreads();

#pragma unroll 8
        for (int kk = 0; kk < BK; kk++) {
            float4 a0 = *reinterpret_cast<const float4*>(&As[kk * LDA + ty * 4]);
            float4 a1 = *reinterpret_cast<const float4*>(&As[kk * LDA + 64 + ty * 4]);
            float4 b4 = *reinterpret_cast<const float4*>(&Bs[kk * BN + tx * 4]);
            float ar[8]  = {a0.x, a0.y, a0.z, a0.w, a1.x, a1.y, a1.z, a1.w};
            float brg[4] = {b4.x, b4.y, b4.z, b4.w};
#pragma unroll
            for (int i = 0; i < 8; i++)
#pragma unroll
                for (int j = 0; j < 4; j++)
                    acc[i][j] = fmaf(ar[i], brg[j], acc[i][j]);
        }
        __syncthreads();
    }

    int ncol = bn0 + tx * 4;
    if (ncol >= Nc) return;
    float4 bv = *reinterpret_cast<const float4*>(bias + ncol);
#pragma unroll
    for (int i = 0; i < 8; i++) {
        int row = bm0 + ((i < 4) ? (ty * 4 + i) : (64 + ty * 4 + (i - 4)));
        if (row < M) {
            float4 o = make_float4(acc[i][0] + bv.x, acc[i][1] + bv.y,
                                   acc[i][2] + bv.z, acc[i][3] + bv.w);
            if (DOSELU) {
                o.x = selu_f(o.x); o.y = selu_f(o.y);
                o.z = selu_f(o.z); o.w = selu_f(o.w);
            }
            *reinterpret_cast<float4*>(C + (size_t)row * Nc + ncol) = o;
        }
    }
}

// ---------------------------------------------------------------------------
// Edge pass 1 (REWRITTEN): We + att held in REGISTERS per lane.
// Lane `l` owns columns {h*32+l : h=0..4} -> needs We[k][h*32+l] (80 floats)
// and att[h*32+l] (5 floats), loaded once per warp, reused over ~84 edges.
// Inner loop is pure register FFMA -- no shared memory at all.
// Butterfly-reduce leaves head sums in ALL lanes; lanes 0..4 store + atomicMax.
// ---------------------------------------------------------------------------
__global__ __launch_bounds__(256, 2)
void edge_score_k(const int* __restrict__ ei, const float* __restrict__ eattr,
                  const float* __restrict__ We, const float* __restrict__ att)
{
    const int lane = threadIdx.x & 31;
    int w        = (blockIdx.x * 256 + threadIdx.x) >> 5;
    const int nw = (gridDim.x * 256) >> 5;

    // --- hoist We / att into registers (coalesced loads, amortized)
    float we_r[H_][ED_];
    float att_r[H_];
#pragma unroll
    for (int h = 0; h < H_; h++) {
        att_r[h] = __ldg(&att[h * 32 + lane]);
#pragma unroll
        for (int k = 0; k < ED_; k++)
            we_r[h][k] = __ldg(&We[k * D_ + h * 32 + lane]);
    }

    for (int e = w; e < E_; e += nw) {
        int src = __ldg(&ei[e]);        // uniform across warp -> broadcast
        int dst = __ldg(&ei[E_ + e]);
        const float* xl = g_xlr + (size_t)src * 320;
        const float* xr = g_xlr + (size_t)dst * 320 + 160;

        // edge features (uniform address -> broadcast loads)
        float ew[ED_];
        const float4* ep = reinterpret_cast<const float4*>(eattr + (size_t)e * ED_);
#pragma unroll
        for (int q = 0; q < ED_ / 4; q++) {
            float4 v = __ldg(ep + q);
            ew[4*q] = v.x; ew[4*q+1] = v.y; ew[4*q+2] = v.z; ew[4*q+3] = v.w;
        }

        float acc[H_];
#pragma unroll
        for (int h = 0; h < H_; h++)
            acc[h] = xl[h * 32 + lane] + xr[h * 32 + lane];
#pragma unroll
        for (int k = 0; k < ED_; k++)
#pragma unroll
            for (int h = 0; h < H_; h++)
                acc[h] = fmaf(ew[k], we_r[h][k], acc[h]);
#pragma unroll
        for (int h = 0; h < H_; h++) {
            float v = acc[h];
            acc[h] = att_r[h] * (v > 0.f ? v : SLOPE_ * v);
        }

        // xor-butterfly: result present in every lane
#pragma unroll
        for (int o = 16; o > 0; o >>= 1)
#pragma unroll
            for (int h = 0; h < H_; h++)
                acc[h] += __shfl_xor_sync(0xffffffffu, acc[h], o);

        if (lane < H_) {
            float v = acc[0];
            if (lane == 1) v = acc[1];
            else if (lane == 2) v = acc[2];
            else if (lane == 3) v = acc[3];
            else if (lane == 4) v = acc[4];
            g_score[(size_t)e * H_ + lane] = v;
            atomicMax(&g_mx[(size_t)dst * H_ + lane], fenc(v));
        }
    }
}

// ---------------------------------------------------------------------------
// Edge pass 2: one THREAD per edge -- single dst load, 5 exps, 5 atomics
// ---------------------------------------------------------------------------
__global__ void edge_exp_k(const int* __restrict__ ei)
{
    int e = blockIdx.x * blockDim.x + threadIdx.x;
    if (e >= E_) return;
    int dst = __ldg(&ei[E_ + e]);
    float*    sp  = g_score + (size_t)e * H_;
    unsigned* mxp = g_mx    + (size_t)dst * H_;
    float*    dp  = g_denom + (size_t)dst * H_;
#pragma unroll
    for (int h = 0; h < H_; h++) {
        float ex = __expf(sp[h] - fdec(mxp[h]));
        sp[h] = ex;
        atomicAdd(&dp[h], ex);
    }
}

// ---------------------------------------------------------------------------
// Edge pass 3: agg[dst] += alpha[e,h] * xl[src]  (vector f32x4 REDs)
// ---------------------------------------------------------------------------
__global__ __launch_bounds__(256)
void edge_agg_k(const int* __restrict__ ei)
{
    const int lane = threadIdx.x & 31;
    int w        = (blockIdx.x * 256 + threadIdx.x) >> 5;
    const int nw = (gridDim.x * 256) >> 5;

    for (int e = w; e < E_; e += nw) {
        int src = __ldg(&ei[e]);
        int dst = __ldg(&ei[E_ + e]);
        float al = 0.f;
        if (lane < H_)
            al = g_score[(size_t)e * H_ + lane] / g_denom[(size_t)dst * H_ + lane];
        float a0 = __shfl_sync(0xffffffffu, al, lane >> 3);  // head of my group
        float a4 = __shfl_sync(0xffffffffu, al, 4);          // head 4

        const float4* xl4 = reinterpret_cast<const float4*>(g_xlr + (size_t)src * 320);
        float4*       ag4 = reinterpret_cast<float4*>(g_agg + (size_t)dst * 160);
        {
            float4 v = __ldg(xl4 + lane);
            asm volatile("red.global.add.v4.f32 [%0], {%1,%2,%3,%4};" ::
                         "l"(ag4 + lane),
                         "f"(a0 * v.x), "f"(a0 * v.y), "f"(a0 * v.z), "f"(a0 * v.w)
                         : "memory");
        }
        if (lane < 8) {
            float4 v = __ldg(xl4 + 32 + lane);
            asm volatile("red.global.add.v4.f32 [%0], {%1,%2,%3,%4};" ::
                         "l"(ag4 + 32 + lane),
                         "f"(a4 * v.x), "f"(a4 * v.y), "f"(a4 * v.z), "f"(a4 * v.w)
                         : "memory");
        }
    }
}

// ---------------------------------------------------------------------------
// LayerNorms (warp per row)
// ---------------------------------------------------------------------------
__global__ void ln1_k(const float* __restrict__ x, const float* __restrict__ bgat,
                      const float* __restrict__ g, const float* __restrict__ b)
{
    const int lane = threadIdx.x & 31;
    int row = (blockIdx.x * blockDim.x + threadIdx.x) >> 5;
    if (row >= N_) return;
    const float* xr = x     + (size_t)row * D_;
    const float* ar = g_agg + (size_t)row * D_;
    float v[H_];
    float s = 0.f, s2 = 0.f;
#pragma unroll
    for (int h = 0; h < H_; h++) {
        int c = h * 32 + lane;
        float t = xr[c] + ar[c] + __ldg(&bgat[c]);
        v[h] = t; s += t; s2 = fmaf(t, t, s2);
    }
#pragma unroll
    for (int o = 16; o > 0; o >>= 1) {
        s  += __shfl_xor_sync(0xffffffffu, s,  o);
        s2 += __shfl_xor_sync(0xffffffffu, s2, o);
    }
    float mean = s * (1.f / D_);
    float var  = s2 * (1.f / D_) - mean * mean;
    float inv  = rsqrtf(var + EPS_);
    float* op = g_out1 + (size_t)row * D_;
#pragma unroll
    for (int h = 0; h < H_; h++) {
        int c = h * 32 + lane;
        op[c] = (v[h] - mean) * inv * __ldg(&g[c]) + __ldg(&b[c]);
    }
}

__global__ void ln_hid_k(const float* __restrict__ g, const float* __restrict__ b)
{
    const int lane = threadIdx.x & 31;
    int row = (blockIdx.x * blockDim.x + threadIdx.x) >> 5;
    if (row >= N_) return;
    float* hp = g_hid + (size_t)row * HID_;
    float4 v[4];
    float s = 0.f, s2 = 0.f;
#pragma unroll
    for (int j = 0; j < 4; j++) {
        v[j] = *reinterpret_cast<const float4*>(hp + j * 128 + lane * 4);
        s += v[j].x + v[j].y + v[j].z + v[j].w;
        s2 = fmaf(v[j].x, v[j].x, fmaf(v[j].y, v[j].y,
             fmaf(v[j].z, v[j].z, fmaf(v[j].w, v[j].w, s2))));
    }
#pragma unroll
    for (int o = 16; o > 0; o >>= 1) {
        s  += __shfl_xor_sync(0xffffffffu, s,  o);
        s2 += __shfl_xor_sync(0xffffffffu, s2, o);
    }
    float mean = s * (1.f / HID_);
    float var  = s2 * (1.f / HID_) - mean * mean;
    float inv  = rsqrtf(var + EPS_);
#pragma unroll
    for (int j = 0; j < 4; j++) {
        int c = j * 128 + lane * 4;
        float4 gg = __ldg(reinterpret_cast<const float4*>(g + c));
        float4 bb = __ldg(reinterpret_cast<const float4*>(b + c));
        float4 o;
        o.x = (v[j].x - mean) * inv * gg.x + bb.x;
        o.y = (v[j].y - mean) * inv * gg.y + bb.y;
        o.z = (v[j].z - mean) * inv * gg.z + bb.z;
        o.w = (v[j].w - mean) * inv * gg.w + bb.w;
        *reinterpret_cast<float4*>(hp + c) = o;
    }
}

__global__ void ln2_k(const float* __restrict__ g, const float* __restrict__ b,
                      float* __restrict__ out)
{
    const int lane = threadIdx.x & 31;
    int row = (blockIdx.x * blockDim.x + threadIdx.x) >> 5;
    if (row >= N_) return;
    const float* r1 = g_out1 + (size_t)row * D_;
    const float* r2 = g_agg  + (size_t)row * D_;
    float v[H_];
    float s = 0.f, s2 = 0.f;
#pragma unroll
    for (int h = 0; h < H_; h++) {
        int c = h * 32 + lane;
        float t = r1[c] + r2[c];
        v[h] = t; s += t; s2 = fmaf(t, t, s2);
    }
#pragma unroll
    for (int o = 16; o > 0; o >>= 1) {
        s  += __shfl_xor_sync(0xffffffffu, s,  o);
        s2 += __shfl_xor_sync(0xffffffffu, s2, o);
    }
    float mean = s * (1.f / D_);
    float var  = s2 * (1.f / D_) - mean * mean;
    float inv  = rsqrtf(var + EPS_);
    float* op = out + (size_t)row * D_;
#pragma unroll
    for (int h = 0; h < H_; h++) {
        int c = h * 32 + lane;
        op[c] = (v[h] - mean) * inv * __ldg(&g[c]) + __ldg(&b[c]);
    }
}

// ---------------------------------------------------------------------------
// Launch
// ---------------------------------------------------------------------------
extern "C" void kernel_launch(void* const* d_in, const int* in_sizes, int n_in,
                              void* d_out, int out_size)
{
    const float* x     = (const float*)d_in[0];
    const int*   ei    = (const int*)  d_in[1];
    const float* eattr = (const float*)d_in[2];
    const float* Wl    = (const float*)d_in[5];
    const float* bl    = (const float*)d_in[6];
    const float* Wr    = (const float*)d_in[7];
    const float* br    = (const float*)d_in[8];
    const float* We    = (const float*)d_in[9];
    const float* att   = (const float*)d_in[10];
    const float* bgat  = (const float*)d_in[11];
    const float* g1    = (const float*)d_in[12];
    const float* b1    = (const float*)d_in[13];
    const float* Wm1   = (const float*)d_in[14];
    const float* bm1   = (const float*)d_in[15];
    const float* gm    = (const float*)d_in[16];
    const float* bm    = (const float*)d_in[17];
    const float* Wm2   = (const float*)d_in[18];
    const float* bm2   = (const float*)d_in[19];
    const float* g2    = (const float*)d_in[20];
    const float* b2    = (const float*)d_in[21];
    float* out = (float*)d_out;

    float *xlr, *Wcat, *bcat, *out1, *hid, *agg;
    cudaGetSymbolAddress((void**)&xlr,  g_xlr);
    cudaGetSymbolAddress((void**)&Wcat, g_Wcat);
    cudaGetSymbolAddress((void**)&bcat, g_bcat);
    cudaGetSymbolAddress((void**)&out1, g_out1);
    cudaGetSymbolAddress((void**)&hid,  g_hid);
    cudaGetSymbolAddress((void**)&agg,  g_agg);

    init_k<<<(N_ * D_ / 4 + 255) / 256, 256>>>();
    prep_w<<<(D_ * 320 + 255) / 256, 256>>>(Wl, bl, Wr, br);

    // xl|xr = x @ [Wl|Wr] + [bl|br]   -> g_xlr [N,320]
    sgemm_k<false><<<dim3(320 / 64, (N_ + 127) / 128), 256>>>(
        x, Wcat, bcat, xlr, N_, 320, D_);

    // GATv2 attention
    edge_score_k<<<1184, 256>>>(ei, eattr, We, att);
    edge_exp_k<<<(E_ + 255) / 256, 256>>>(ei);
    edge_agg_k<<<1184, 256>>>(ei);

    // out1 = LN(x + agg + b_gat)
    ln1_k<<<(N_ + 7) / 8, 256>>>(x, bgat, g1, b1);

    // hid = selu(out1 @ W_m1 + b_m1), then LN in place
    sgemm_k<true><<<dim3(HID_ / 64, (N_ + 127) / 128), 256>>>(
        out1, Wm1, bm1, hid, N_, HID_, D_);
    ln_hid_k<<<(N_ + 7) / 8, 256>>>(gm, bm);

    // mlp = hid @ W_m2 + b_m2  (reuse g_agg)
    sgemm_k<false><<<dim3((D_ + 63) / 64, (N_ + 127) / 128), 256>>>(
        hid, Wm2, bm2, agg, N_, D_, HID_);

    // out = LN(out1 + mlp)
    ln2_k<<<(N_ + 7) / 8, 256>>>(g2, b2, out);
}